// round 3
// baseline (speedup 1.0000x reference)
#include <cuda_runtime.h>
#include <cuda_bf16.h>

// Problem dims
#define K_DIM 8192
#define N_DIM 8192
#define BATCH 32

// GEMM tiling
#define KSPLIT 4
#define KCHUNK (K_DIM / KSPLIT)          // 2048
#define WARPS_PER_CTA 8
#define WARP_N 32                        // 4 n-tiles of 8 per warp
#define CTA_N (WARPS_PER_CTA * WARP_N)   // 256
#define NCTAS (N_DIM / CTA_N)            // 32

// Scratch (allocation-free: __device__ globals)
// A: 64 rows = 32 hi rows (bf16 of x*scaler) + 32 lo rows (bf16 residual)
__device__ __nv_bfloat16 g_A[64 * K_DIM];          // 1 MB
__device__ float g_Yp[KSPLIT][64 * N_DIM];         // 8 MB partials

// ---------------------------------------------------------------------------
// Kernel 1: fold scaler into x, split into bf16 hi/lo rows of A.
// ---------------------------------------------------------------------------
__global__ void prep_kernel(const float* __restrict__ x,
                            const float* __restrict__ scaler) {
    int idx = blockIdx.x * blockDim.x + threadIdx.x;   // 0 .. 32*8192-1
    float s = scaler[0];
    float xs = x[idx] * s;
    __nv_bfloat16 hi = __float2bfloat16_rn(xs);
    float lo_f = xs - __bfloat162float(hi);            // exact in fp32
    __nv_bfloat16 lo = __float2bfloat16_rn(lo_f);
    int b = idx >> 13;                                 // / 8192
    int k = idx & (K_DIM - 1);
    g_A[b * K_DIM + k] = hi;
    g_A[(b + 32) * K_DIM + k] = lo;
}

// ---------------------------------------------------------------------------
// Kernel 2: fused dequant GEMM via mma.sync m16n8k16 bf16.
// Each warp: m = 64 (4 m-tiles), n = 32 (4 n-tiles), k = KCHUNK.
// ---------------------------------------------------------------------------
__global__ __launch_bounds__(256) void gemm_kernel(const int* __restrict__ W) {
    const int lane = threadIdx.x & 31;
    const int warp = threadIdx.x >> 5;
    const int g  = lane >> 2;      // group id (0..7)
    const int tg = lane & 3;       // thread-in-group (0..3)

    const int n0   = blockIdx.x * CTA_N + warp * WARP_N;
    const int kbeg = blockIdx.y * KCHUNK;
    const int kend = kbeg + KCHUNK;

    float acc[4][4][4];
    #pragma unroll
    for (int t = 0; t < 4; t++)
        #pragma unroll
        for (int i = 0; i < 4; i++)
            #pragma unroll
            for (int j = 0; j < 4; j++)
                acc[t][i][j] = 0.0f;

    for (int k = kbeg; k < kend; k += 16) {
        const int ka = k + tg * 2;

        // A fragments (bf16x2 pairs), same for every warp in the CTA -> L1 broadcast
        unsigned a[4][4];
        #pragma unroll
        for (int t = 0; t < 4; t++) {
            const int r0 = t * 16 + g;
            a[t][0] = *reinterpret_cast<const unsigned*>(&g_A[r0 * K_DIM + ka]);
            a[t][1] = *reinterpret_cast<const unsigned*>(&g_A[(r0 + 8) * K_DIM + ka]);
            a[t][2] = *reinterpret_cast<const unsigned*>(&g_A[r0 * K_DIM + ka + 8]);
            a[t][3] = *reinterpret_cast<const unsigned*>(&g_A[(r0 + 8) * K_DIM + ka + 8]);
        }

        #pragma unroll
        for (int i = 0; i < 4; i++) {
            const int n = n0 + i * 8 + g;
            const int* wp = W + (size_t)ka * N_DIM + n;
            // B fragment: rows (k) {ka, ka+1, ka+8, ka+9}, col n
            int w0 = wp[0];
            int w1 = wp[N_DIM];
            int w2 = wp[8 * N_DIM];
            int w3 = wp[9 * N_DIM];
            float f0 = (float)w0, f1 = (float)w1, f2 = (float)w2, f3 = (float)w3;
            unsigned b0, b1;
            // cvt.rn.bf16x2.f32 d, a, b  ->  high = a, low = b.  Low half = even k.
            asm("cvt.rn.bf16x2.f32 %0, %1, %2;" : "=r"(b0) : "f"(f1), "f"(f0));
            asm("cvt.rn.bf16x2.f32 %0, %1, %2;" : "=r"(b1) : "f"(f3), "f"(f2));

            #pragma unroll
            for (int t = 0; t < 4; t++) {
                float* c = acc[t][i];
                asm volatile(
                    "mma.sync.aligned.m16n8k16.row.col.f32.bf16.bf16.f32 "
                    "{%0,%1,%2,%3}, {%4,%5,%6,%7}, {%8,%9}, {%0,%1,%2,%3};"
                    : "+f"(c[0]), "+f"(c[1]), "+f"(c[2]), "+f"(c[3])
                    : "r"(a[t][0]), "r"(a[t][1]), "r"(a[t][2]), "r"(a[t][3]),
                      "r"(b0), "r"(b1));
            }
        }
    }

    // Epilogue: write fp32 partials.
    float* yp_base = g_Yp[blockIdx.y];
    #pragma unroll
    for (int t = 0; t < 4; t++) {
        #pragma unroll
        for (int i = 0; i < 4; i++) {
            const int row = t * 16 + g;
            const int col = n0 + i * 8 + tg * 2;
            float2 v01 = make_float2(acc[t][i][0], acc[t][i][1]);
            float2 v23 = make_float2(acc[t][i][2], acc[t][i][3]);
            *reinterpret_cast<float2*>(&yp_base[row * N_DIM + col]) = v01;
            *reinterpret_cast<float2*>(&yp_base[(row + 8) * N_DIM + col]) = v23;
        }
    }
}

// ---------------------------------------------------------------------------
// Kernel 3: reduce k-splits and hi+lo row pairs into the final output.
// ---------------------------------------------------------------------------
__global__ void reduce_kernel(float* __restrict__ out) {
    int idx = blockIdx.x * blockDim.x + threadIdx.x;   // 0 .. 32*8192-1
    int b = idx >> 13;
    int n = idx & (N_DIM - 1);
    float s = 0.0f;
    #pragma unroll
    for (int sp = 0; sp < KSPLIT; sp++) {
        s += g_Yp[sp][b * N_DIM + n];
        s += g_Yp[sp][(b + 32) * N_DIM + n];
    }
    out[idx] = s;
}

// ---------------------------------------------------------------------------
extern "C" void kernel_launch(void* const* d_in, const int* in_sizes, int n_in,
                              void* d_out, int out_size) {
    const float* x      = (const float*)d_in[0];   // [32, 8192] fp32
    const int*   w      = (const int*)d_in[1];     // [8192, 8192] int32 (int8-valued)
    const float* scaler = (const float*)d_in[2];   // [1] fp32
    float* out = (float*)d_out;                    // [32, 8192] fp32

    prep_kernel<<<512, 512>>>(x, scaler);
    gemm_kernel<<<dim3(NCTAS, KSPLIT), 256>>>(w);
    reduce_kernel<<<512, 512>>>(out);
}

// round 4
// speedup vs baseline: 2.1306x; 2.1306x over previous
#include <cuda_runtime.h>
#include <cuda_bf16.h>
#include <cstdint>

// Problem dims
#define K_DIM 8192
#define N_DIM 8192

// GEMM tiling
#define KSPLIT 4
#define KCHUNK (K_DIM / KSPLIT)          // 2048
#define NKSTEPS (KCHUNK / 16)            // 128 k-steps of 16
#define CTA_N 128
#define NSTRIPS (N_DIM / CTA_N)          // 64
#define WARPS 8
#define WARP_N 16                        // 2 n-tiles of 8 per warp
#define STAGES 4

// Shared-memory stage layout
#define W_ROW_BYTES (CTA_N * 4)                  // 512
#define W_ROW_STRIDE (W_ROW_BYTES + 16)          // 528 (pad -> conflict-free frag LDS)
#define W_STAGE_BYTES (16 * W_ROW_STRIDE)        // 8448
#define A_STAGE_BYTES 2048                       // 4 t-tiles * 32 lanes * 16B
#define STAGE_BYTES (W_STAGE_BYTES + A_STAGE_BYTES)  // 10496
#define SMEM_BYTES (STAGES * STAGE_BYTES)        // 41984 (< 48KB static limit)

// Scratch (allocation-free: __device__ globals)
// A packed in exact m16n8k16 A-fragment order:
// [kstep][t][lane][4 x b32 regs] ; rows 0-31 = bf16 hi of x*scaler, 32-63 = bf16 lo residual
__device__ __align__(16) __nv_bfloat16 g_Apack[64 * K_DIM];   // 1 MB
__device__ float g_Yp[KSPLIT][64 * N_DIM];                    // 8 MB partials

// ---------------------------------------------------------------------------
// Kernel 1: fold scaler into x, split bf16 hi/lo, write fragment-packed A.
// One thread per (row r in 0..63, k-pair). Packs bf16x2 and scatters to the
// fragment slot so the GEMM can fetch A with LDS.128.
// ---------------------------------------------------------------------------
__global__ void prep_pack_kernel(const float* __restrict__ x,
                                 const float* __restrict__ scaler) {
    int idx = blockIdx.x * blockDim.x + threadIdx.x;   // 0 .. 64*4096-1
    int r  = idx >> 12;          // logical A row 0..63
    int kp = idx & 4095;         // k pair index
    int k  = kp * 2;
    int b  = r & 31;
    float s = scaler[0];
    float xs0 = x[b * K_DIM + k] * s;
    float xs1 = x[b * K_DIM + k + 1] * s;
    __nv_bfloat16 h0 = __float2bfloat16_rn(xs0);
    __nv_bfloat16 h1 = __float2bfloat16_rn(xs1);
    if (r >= 32) {               // lo-residual plane
        h0 = __float2bfloat16_rn(xs0 - __bfloat162float(h0));
        h1 = __float2bfloat16_rn(xs1 - __bfloat162float(h1));
    }
    unsigned packed = ((unsigned)__bfloat16_as_ushort(h1) << 16) |
                      (unsigned)__bfloat16_as_ushort(h0);
    // Fragment address: slot order {a0,a1,a2,a3} = {(g,klo),(g+8,klo),(g,khi),(g+8,khi)}
    int ks = k >> 4;
    int kk = k & 15;
    int t  = r >> 4;
    int gg = r & 15;
    int gq = gg & 7;
    int tg = (kk >> 1) & 3;
    int slot = ((kk >> 3) << 1) | (gg >> 3);
    size_t off = (size_t)ks * A_STAGE_BYTES + t * 512 + (gq * 4 + tg) * 16 + slot * 4;
    *(unsigned*)((char*)g_Apack + off) = packed;
}

// ---------------------------------------------------------------------------
// Kernel 2: cp.async-pipelined fused dequant GEMM (mma.sync m16n8k16 bf16).
// CTA: 128 n-cols, 8 warps (warp_n = 16, m = 64). 4-stage smem pipeline.
// ---------------------------------------------------------------------------
__global__ __launch_bounds__(256, 2) void gemm_kernel(const int* __restrict__ W) {
    __shared__ __align__(16) char sm[SMEM_BYTES];

    const int tid  = threadIdx.x;
    const int lane = tid & 31;
    const int warp = tid >> 5;
    const int g    = lane >> 2;
    const int tg   = lane & 3;

    const int n0cta = blockIdx.x * CTA_N;
    const int krow0 = blockIdx.y * KCHUNK;     // first k row of this split
    const int ks0   = blockIdx.y * NKSTEPS;    // first global kstep (for A pack)

    // cp.async thread coords: each thread copies two 16B W granules + one 8B A granule
    const int r0  = tid >> 5;                  // W tile row 0..7 (and +8)
    const int c16 = tid & 31;                  // 16B column granule within row
    const char* wsrc0 = (const char*)(W + (size_t)(krow0 + r0) * N_DIM + n0cta + c16 * 4);
    const char* asrc0 = (const char*)g_Apack + (size_t)ks0 * A_STAGE_BYTES + tid * 8;
    const unsigned sm_base = (unsigned)__cvta_generic_to_shared(sm);

    auto issue_stage = [&](int p) {
        if (p < NKSTEPS) {
            unsigned d  = sm_base + (p & (STAGES - 1)) * STAGE_BYTES;
            const char* ws = wsrc0 + (size_t)p * 16 * N_DIM * 4;
            unsigned d0 = d + r0 * W_ROW_STRIDE + c16 * 16;
            asm volatile("cp.async.cg.shared.global [%0], [%1], 16;\n"
                         :: "r"(d0), "l"(ws));
            asm volatile("cp.async.cg.shared.global [%0], [%1], 16;\n"
                         :: "r"(d0 + 8 * W_ROW_STRIDE), "l"(ws + (size_t)8 * N_DIM * 4));
            asm volatile("cp.async.ca.shared.global [%0], [%1], 8;\n"
                         :: "r"(d + W_STAGE_BYTES + tid * 8),
                            "l"(asrc0 + (size_t)p * A_STAGE_BYTES));
        }
        asm volatile("cp.async.commit_group;\n" ::);
    };

    issue_stage(0);
    issue_stage(1);
    issue_stage(2);

    float acc[4][2][4] = {};

    for (int ks = 0; ks < NKSTEPS; ks++) {
        asm volatile("cp.async.wait_group 2;\n" ::);
        __syncthreads();
        issue_stage(ks + 3);   // refills the buffer consumed at iteration ks-1

        const unsigned sb = sm_base + (ks & (STAGES - 1)) * STAGE_BYTES;

        // A fragments: 4 x LDS.128 from the packed A slice (broadcast across warps)
        unsigned a[4][4];
        const unsigned ab = sb + W_STAGE_BYTES + lane * 16;
        #pragma unroll
        for (int t = 0; t < 4; t++) {
            asm volatile("ld.shared.v4.b32 {%0,%1,%2,%3}, [%4];"
                         : "=r"(a[t][0]), "=r"(a[t][1]), "=r"(a[t][2]), "=r"(a[t][3])
                         : "r"(ab + t * 512));
        }

        #pragma unroll
        for (int i = 0; i < 2; i++) {
            // B fragment ints from smem: rows tg*2 + {0,1,8,9}, col warp*16 + i*8 + g.
            // Row stride 528B -> bank = 8*tg + g + const : conflict-free.
            const unsigned wb = sb + (tg * 2) * W_ROW_STRIDE + (warp * WARP_N + i * 8 + g) * 4;
            int w0, w1, w2, w3;
            asm volatile("ld.shared.b32 %0, [%1];" : "=r"(w0) : "r"(wb));
            asm volatile("ld.shared.b32 %0, [%1];" : "=r"(w1) : "r"(wb + W_ROW_STRIDE));
            asm volatile("ld.shared.b32 %0, [%1];" : "=r"(w2) : "r"(wb + 8 * W_ROW_STRIDE));
            asm volatile("ld.shared.b32 %0, [%1];" : "=r"(w3) : "r"(wb + 9 * W_ROW_STRIDE));
            float f0 = (float)w0, f1 = (float)w1, f2 = (float)w2, f3 = (float)w3;
            unsigned b0, b1;
            asm("cvt.rn.bf16x2.f32 %0, %1, %2;" : "=r"(b0) : "f"(f1), "f"(f0));
            asm("cvt.rn.bf16x2.f32 %0, %1, %2;" : "=r"(b1) : "f"(f3), "f"(f2));

            #pragma unroll
            for (int t = 0; t < 4; t++) {
                float* c = acc[t][i];
                asm volatile(
                    "mma.sync.aligned.m16n8k16.row.col.f32.bf16.bf16.f32 "
                    "{%0,%1,%2,%3}, {%4,%5,%6,%7}, {%8,%9}, {%0,%1,%2,%3};"
                    : "+f"(c[0]), "+f"(c[1]), "+f"(c[2]), "+f"(c[3])
                    : "r"(a[t][0]), "r"(a[t][1]), "r"(a[t][2]), "r"(a[t][3]),
                      "r"(b0), "r"(b1));
            }
        }
    }

    // Epilogue: fp32 partials
    float* yp = g_Yp[blockIdx.y];
    #pragma unroll
    for (int t = 0; t < 4; t++) {
        #pragma unroll
        for (int i = 0; i < 2; i++) {
            const int row = t * 16 + g;
            const int col = n0cta + warp * WARP_N + i * 8 + tg * 2;
            *reinterpret_cast<float2*>(&yp[(size_t)row * N_DIM + col]) =
                make_float2(acc[t][i][0], acc[t][i][1]);
            *reinterpret_cast<float2*>(&yp[(size_t)(row + 8) * N_DIM + col]) =
                make_float2(acc[t][i][2], acc[t][i][3]);
        }
    }
}

// ---------------------------------------------------------------------------
// Kernel 3: reduce k-splits and hi+lo row pairs into the final output.
// ---------------------------------------------------------------------------
__global__ void reduce_kernel(float* __restrict__ out) {
    int idx = blockIdx.x * blockDim.x + threadIdx.x;   // 0 .. 32*8192-1
    int b = idx >> 13;
    int n = idx & (N_DIM - 1);
    float s = 0.0f;
    #pragma unroll
    for (int sp = 0; sp < KSPLIT; sp++) {
        s += g_Yp[sp][b * N_DIM + n];
        s += g_Yp[sp][(b + 32) * N_DIM + n];
    }
    out[idx] = s;
}

// ---------------------------------------------------------------------------
extern "C" void kernel_launch(void* const* d_in, const int* in_sizes, int n_in,
                              void* d_out, int out_size) {
    const float* x      = (const float*)d_in[0];   // [32, 8192] fp32
    const int*   w      = (const int*)d_in[1];     // [8192, 8192] int32 (int8-valued)
    const float* scaler = (const float*)d_in[2];   // [1] fp32
    float* out = (float*)d_out;                    // [32, 8192] fp32

    prep_pack_kernel<<<1024, 256>>>(x, scaler);
    gemm_kernel<<<dim3(NSTRIPS, KSPLIT), 256>>>(w);
    reduce_kernel<<<512, 512>>>(out);
}

// round 5
// speedup vs baseline: 2.3914x; 1.1224x over previous
#include <cuda_runtime.h>
#include <cuda_fp16.h>
#include <cstdint>

// Problem dims
#define K_DIM 8192
#define N_DIM 8192

// GEMM tiling
#define KSPLIT 4
#define KCHUNK (K_DIM / KSPLIT)          // 2048
#define NKSTEPS (KCHUNK / 16)            // 128 k-steps of 16
#define CTA_N 128
#define NSTRIPS (N_DIM / CTA_N)          // 64
#define WARPS 8
#define WARP_N 16                        // 2 n-tiles of 8 per warp
#define STAGES 4

// Shared-memory stage layout
#define W_ROW_BYTES (CTA_N * 4)                  // 512
#define W_ROW_STRIDE (W_ROW_BYTES + 16)          // 528 (pad -> conflict-free frag LDS)
#define W_STAGE_BYTES (16 * W_ROW_STRIDE)        // 8448
#define A_STAGE_BYTES 1024                       // 2 t-tiles * 32 lanes * 16B
#define STAGE_BYTES (W_STAGE_BYTES + A_STAGE_BYTES)  // 9472
#define SMEM_BYTES (STAGES * STAGE_BYTES)        // 37888 (< 48KB static limit)

// Scratch (allocation-free: __device__ globals)
// A packed in exact m16n8k16 A-fragment order (fp16 of x*scaler):
// [kstep][t][lane][4 x b32 regs], 32 rows.
__device__ __align__(16) __half g_Apack[32 * K_DIM];    // 512 KB
__device__ float g_Yp[KSPLIT][32 * N_DIM];              // 4 MB partials

// ---------------------------------------------------------------------------
// Kernel 1: fold scaler into x, convert to fp16, write fragment-packed A.
// One thread per (row r in 0..31, k-pair).
// ---------------------------------------------------------------------------
__global__ void prep_pack_kernel(const float* __restrict__ x,
                                 const float* __restrict__ scaler) {
    int idx = blockIdx.x * blockDim.x + threadIdx.x;   // 0 .. 32*4096-1
    int r  = idx >> 12;          // A row 0..31
    int kp = idx & 4095;         // k pair index
    int k  = kp * 2;
    float s = scaler[0];
    float xs0 = x[r * K_DIM + k] * s;
    float xs1 = x[r * K_DIM + k + 1] * s;
    __half2 h2 = __floats2half2_rn(xs0, xs1);          // low = xs0 (even k)
    unsigned packed = *reinterpret_cast<unsigned*>(&h2);
    // Fragment address: slot order {a0,a1,a2,a3} = {(g,klo),(g+8,klo),(g,khi),(g+8,khi)}
    int ks = k >> 4;
    int kk = k & 15;
    int t  = r >> 4;             // 0..1
    int gg = r & 15;
    int gq = gg & 7;
    int tg = (kk >> 1) & 3;
    int slot = ((kk >> 3) << 1) | (gg >> 3);
    size_t off = (size_t)ks * A_STAGE_BYTES + t * 512 + (gq * 4 + tg) * 16 + slot * 4;
    *(unsigned*)((char*)g_Apack + off) = packed;
}

// ---------------------------------------------------------------------------
// Kernel 2: cp.async-pipelined fused dequant GEMM (mma.sync m16n8k16 f16.f32).
// CTA: 128 n-cols, 8 warps (warp_n = 16, m = 32). 4-stage smem pipeline.
// ---------------------------------------------------------------------------
__global__ __launch_bounds__(256, 2) void gemm_kernel(const int* __restrict__ W) {
    __shared__ __align__(16) char sm[SMEM_BYTES];

    const int tid  = threadIdx.x;
    const int lane = tid & 31;
    const int warp = tid >> 5;
    const int g    = lane >> 2;
    const int tg   = lane & 3;

    const int n0cta = blockIdx.x * CTA_N;
    const int krow0 = blockIdx.y * KCHUNK;     // first k row of this split
    const int ks0   = blockIdx.y * NKSTEPS;    // first global kstep (for A pack)

    // cp.async thread coords: each thread copies two 16B W granules + one 4B A granule
    const int r0  = tid >> 5;                  // W tile row 0..7 (and +8)
    const int c16 = tid & 31;                  // 16B column granule within row
    const char* wsrc0 = (const char*)(W + (size_t)(krow0 + r0) * N_DIM + n0cta + c16 * 4);
    const char* asrc0 = (const char*)g_Apack + (size_t)ks0 * A_STAGE_BYTES + tid * 4;
    const unsigned sm_base = (unsigned)__cvta_generic_to_shared(sm);

    auto issue_stage = [&](int p) {
        if (p < NKSTEPS) {
            unsigned d  = sm_base + (p & (STAGES - 1)) * STAGE_BYTES;
            const char* ws = wsrc0 + (size_t)p * 16 * N_DIM * 4;
            unsigned d0 = d + r0 * W_ROW_STRIDE + c16 * 16;
            asm volatile("cp.async.cg.shared.global [%0], [%1], 16;\n"
                         :: "r"(d0), "l"(ws));
            asm volatile("cp.async.cg.shared.global [%0], [%1], 16;\n"
                         :: "r"(d0 + 8 * W_ROW_STRIDE), "l"(ws + (size_t)8 * N_DIM * 4));
            asm volatile("cp.async.ca.shared.global [%0], [%1], 4;\n"
                         :: "r"(d + W_STAGE_BYTES + tid * 4),
                            "l"(asrc0 + (size_t)p * A_STAGE_BYTES));
        }
        asm volatile("cp.async.commit_group;\n" ::);
    };

    issue_stage(0);
    issue_stage(1);
    issue_stage(2);

    float acc[2][2][4] = {};

    for (int ks = 0; ks < NKSTEPS; ks++) {
        asm volatile("cp.async.wait_group 2;\n" ::);
        __syncthreads();
        issue_stage(ks + 3);   // refills the buffer consumed at iteration ks-1

        const unsigned sb = sm_base + (ks & (STAGES - 1)) * STAGE_BYTES;

        // A fragments: 2 x LDS.128 from the packed A slice (broadcast across warps)
        unsigned a[2][4];
        const unsigned ab = sb + W_STAGE_BYTES + lane * 16;
        #pragma unroll
        for (int t = 0; t < 2; t++) {
            asm volatile("ld.shared.v4.b32 {%0,%1,%2,%3}, [%4];"
                         : "=r"(a[t][0]), "=r"(a[t][1]), "=r"(a[t][2]), "=r"(a[t][3])
                         : "r"(ab + t * 512));
        }

        #pragma unroll
        for (int i = 0; i < 2; i++) {
            // B fragment ints from smem: rows tg*2 + {0,1,8,9}, col warp*16 + i*8 + g.
            // Row stride 528B -> bank = 8*tg + g + const : conflict-free.
            const unsigned wb = sb + (tg * 2) * W_ROW_STRIDE + (warp * WARP_N + i * 8 + g) * 4;
            int w0, w1, w2, w3;
            asm volatile("ld.shared.b32 %0, [%1];" : "=r"(w0) : "r"(wb));
            asm volatile("ld.shared.b32 %0, [%1];" : "=r"(w1) : "r"(wb + W_ROW_STRIDE));
            asm volatile("ld.shared.b32 %0, [%1];" : "=r"(w2) : "r"(wb + 8 * W_ROW_STRIDE));
            asm volatile("ld.shared.b32 %0, [%1];" : "=r"(w3) : "r"(wb + 9 * W_ROW_STRIDE));
            __half2 p0 = __floats2half2_rn((float)w0, (float)w1);   // low = even k
            __half2 p1 = __floats2half2_rn((float)w2, (float)w3);
            unsigned b0 = *reinterpret_cast<unsigned*>(&p0);
            unsigned b1 = *reinterpret_cast<unsigned*>(&p1);

            #pragma unroll
            for (int t = 0; t < 2; t++) {
                float* c = acc[t][i];
                asm volatile(
                    "mma.sync.aligned.m16n8k16.row.col.f32.f16.f16.f32 "
                    "{%0,%1,%2,%3}, {%4,%5,%6,%7}, {%8,%9}, {%0,%1,%2,%3};"
                    : "+f"(c[0]), "+f"(c[1]), "+f"(c[2]), "+f"(c[3])
                    : "r"(a[t][0]), "r"(a[t][1]), "r"(a[t][2]), "r"(a[t][3]),
                      "r"(b0), "r"(b1));
            }
        }
    }

    // Epilogue: fp32 partials
    float* yp = g_Yp[blockIdx.y];
    #pragma unroll
    for (int t = 0; t < 2; t++) {
        #pragma unroll
        for (int i = 0; i < 2; i++) {
            const int row = t * 16 + g;
            const int col = n0cta + warp * WARP_N + i * 8 + tg * 2;
            *reinterpret_cast<float2*>(&yp[(size_t)row * N_DIM + col]) =
                make_float2(acc[t][i][0], acc[t][i][1]);
            *reinterpret_cast<float2*>(&yp[(size_t)(row + 8) * N_DIM + col]) =
                make_float2(acc[t][i][2], acc[t][i][3]);
        }
    }
}

// ---------------------------------------------------------------------------
// Kernel 3: reduce k-splits into the final output.
// ---------------------------------------------------------------------------
__global__ void reduce_kernel(float* __restrict__ out) {
    int idx = blockIdx.x * blockDim.x + threadIdx.x;   // 0 .. 32*8192-1
    float s = 0.0f;
    #pragma unroll
    for (int sp = 0; sp < KSPLIT; sp++)
        s += g_Yp[sp][idx];
    out[idx] = s;
}

// ---------------------------------------------------------------------------
extern "C" void kernel_launch(void* const* d_in, const int* in_sizes, int n_in,
                              void* d_out, int out_size) {
    const float* x      = (const float*)d_in[0];   // [32, 8192] fp32
    const int*   w      = (const int*)d_in[1];     // [8192, 8192] int32 (int8-valued)
    const float* scaler = (const float*)d_in[2];   // [1] fp32
    float* out = (float*)d_out;                    // [32, 8192] fp32

    prep_pack_kernel<<<512, 256>>>(x, scaler);
    gemm_kernel<<<dim3(NSTRIPS, KSPLIT), 256>>>(w);
    reduce_kernel<<<512, 512>>>(out);
}